// round 16
// baseline (speedup 1.0000x reference)
#include <cuda_runtime.h>

#define NEG (-1e30f)
#define LOG2E 1.4426950408889634f
#define LN2   0.6931471805599453f

constexpr int B  = 8;
constexpr int T  = 200;
constexpr int U1 = 101;
constexpr int V  = 512;
constexpr int U  = U1 - 1;
constexpr int D  = T + U1 - 1;           // 300 anti-diagonals
constexpr int NCELL = B * T * U1;
constexpr int SB = 102;                  // padded row stride (lane stride 1-SB ≡ 27 mod 32: conflict-free)

// Padded log2-prob tables: [b][t*SB + u]  (pre-scaled by log2 e)
__device__ float g_blank[B * T * SB];
__device__ float g_emit [B * T * SB];
__device__ float g_loss [B];
__device__ int   g_ctr;

__device__ __forceinline__ float ex2_(float x) {
    float r; asm("ex2.approx.ftz.f32 %0, %1;" : "=f"(r) : "f"(x)); return r;
}
__device__ __forceinline__ float lg2_(float x) {
    float r; asm("lg2.approx.ftz.f32 %0, %1;" : "=f"(r) : "f"(x)); return r;
}
__device__ __forceinline__ float laddexp2(float a, float b) {
    float mx = fmaxf(a, b);
    float dd = -fabsf(a - b);
    return mx + lg2_(1.0f + ex2_(dd));
}

// One warp per (b,t,u) cell: logsumexp over V=512; dead cells skipped;
// logits read-once via __ldcs (evict-first).
__global__ void __launch_bounds__(256) k_lse(const float* __restrict__ logits,
                                             const int*   __restrict__ targets,
                                             const int*   __restrict__ fbank_len,
                                             const int*   __restrict__ text_len) {
    int gw   = (blockIdx.x * blockDim.x + threadIdx.x) >> 5;
    int lane = threadIdx.x & 31;
    if (gw >= NCELL) return;

    int u = gw % U1;
    int t = (gw / U1) % T;
    int b = gw / (U1 * T);

    int lab_len = text_len[b] - 1;
    if (t >= fbank_len[b] || u > lab_len) return;   // never consumed by the DP

    const float4* p = reinterpret_cast<const float4*>(logits) + (size_t)gw * (V / 4);
    float4 v0 = __ldcs(p + lane);
    float4 v1 = __ldcs(p + lane + 32);
    float4 v2 = __ldcs(p + lane + 64);
    float4 v3 = __ldcs(p + lane + 96);

    float m = fmaxf(fmaxf(fmaxf(v0.x, v0.y), fmaxf(v0.z, v0.w)),
                    fmaxf(fmaxf(fmaxf(v1.x, v1.y), fmaxf(v1.z, v1.w)),
                          fmaxf(fmaxf(fmaxf(v2.x, v2.y), fmaxf(v2.z, v2.w)),
                                fmaxf(fmaxf(v3.x, v3.y), fmaxf(v3.z, v3.w)))));
#pragma unroll
    for (int o = 16; o; o >>= 1) m = fmaxf(m, __shfl_xor_sync(0xffffffffu, m, o));

    float s = __expf(v0.x - m) + __expf(v0.y - m) + __expf(v0.z - m) + __expf(v0.w - m)
            + __expf(v1.x - m) + __expf(v1.y - m) + __expf(v1.z - m) + __expf(v1.w - m)
            + __expf(v2.x - m) + __expf(v2.y - m) + __expf(v2.z - m) + __expf(v2.w - m)
            + __expf(v3.x - m) + __expf(v3.y - m) + __expf(v3.z - m) + __expf(v3.w - m);
#pragma unroll
    for (int o = 16; o; o >>= 1) s += __shfl_xor_sync(0xffffffffu, s, o);

    float lse = m + __logf(s);

    size_t base = (size_t)b * T * SB + t * SB + u;
    if (lane == 0) g_blank[base] = (v0.x - lse) * LOG2E;

    int lab = (u < U) ? targets[b * U1 + u + 1] : -1;
    if (lab >= 0) {
        int chunk = lab >> 2;
        if ((chunk & 31) == lane) {
            int j = chunk >> 5, c = lab & 3;
            float4 vv = (j == 0) ? v0 : (j == 1) ? v1 : (j == 2) ? v2 : v3;
            float ev  = (c == 0) ? vv.x : (c == 1) ? vv.y : (c == 2) ? vv.z : vv.w;
            g_emit[base] = (ev - lse) * LOG2E;
        }
    }
}

// Single-warp shfl DP (barrier-free): lane holds cells u = lane + 32j (j=0..3)
// in registers. P[u-1] via one rotate-shfl per step. Tables smem-resident,
// 1-step prefetch with running offsets. MUFU-intrinsic logaddexp.
constexpr int SMEM_DP = 2 * T * SB * (int)sizeof(float);

__global__ void __launch_bounds__(256, 1) k_dp(const int* __restrict__ fbank_len,
                                               const int* __restrict__ text_len,
                                               float* __restrict__ out) {
    extern __shared__ float sm[];
    float* smb = sm;                     // blank [T][SB]
    float* sme = sm + T * SB;            // emit  [T][SB]

    int b   = blockIdx.x;
    int tid = threadIdx.x;

    {   // Stage tables with all 256 threads (float4, layout matches padded gmem)
        const float4* gb4 = reinterpret_cast<const float4*>(g_blank + (size_t)b * T * SB);
        const float4* ge4 = reinterpret_cast<const float4*>(g_emit  + (size_t)b * T * SB);
        float4* sb4 = reinterpret_cast<float4*>(smb);
        float4* se4 = reinterpret_cast<float4*>(sme);
        for (int i = tid; i < T * SB / 4; i += 256) { sb4[i] = gb4[i]; se4[i] = ge4[i]; }
    }
    __syncthreads();
    if (tid >= 32) return;               // warp 0 runs the whole DP

    int lane    = tid;
    int lab_len = text_len[b] - 1;
    int tfin    = fbank_len[b] - 1;
    int dfin    = tfin + lab_len;
    int src     = (lane + 31) & 31;      // rotate-left source

    // p[j] = alpha(d, u_j), u_j = lane + 32j  (log2 domain), d = 0 init
    float p0 = (lane == 0) ? 0.0f : NEG;
    float p1 = NEG, p2 = NEG, p3 = NEG;
    float afin = NEG;

    // running smem offsets for diagonal d (start at d = 1):
    //   blank(t-1, u): (d-1-u)*SB + u ;  emit(t, u-1): (d-u)*SB + u - 1
    int u0 = lane, u1 = lane + 32, u2 = lane + 64, u3 = lane + 96;
    int ob0 = (0 - u0) * SB + u0, ob1 = (0 - u1) * SB + u1,
        ob2 = (0 - u2) * SB + u2, ob3 = (0 - u3) * SB + u3;
    int oe0 = (1 - u0) * SB + u0 - 1, oe1 = (1 - u1) * SB + u1 - 1,
        oe2 = (1 - u2) * SB + u2 - 1, oe3 = (1 - u3) * SB + u3 - 1;

    // validity: blank load at diag d needs u+1 <= d <= u+T-1; emit needs
    // max(u,1) <= d <= u+T-1 and u <= U. Prefetch for d = 1:
    float nb0, nb1, nb2, nb3, ne0, ne1, ne2, ne3;
    {
        int d = 1;
        nb0 = (d >= u0 + 1 && d <= u0 + T - 1) ? smb[ob0] : NEG;
        nb1 = (d >= u1 + 1 && d <= u1 + T - 1) ? smb[ob1] : NEG;
        nb2 = (d >= u2 + 1 && d <= u2 + T - 1) ? smb[ob2] : NEG;
        nb3 = (d >= u3 + 1 && d <= u3 + T - 1) ? smb[ob3] : NEG;
        ne0 = (u0 >= 1 && u0 <= U && d >= u0 && d <= u0 + T - 1) ? sme[oe0] : NEG;
        ne1 = (u1 >= 1 && u1 <= U && d >= u1 && d <= u1 + T - 1) ? sme[oe1] : NEG;
        ne2 = (u2 <= U && d >= u2 && d <= u2 + T - 1) ? sme[oe2] : NEG;
        ne3 = (u3 <= U && d >= u3 && d <= u3 + T - 1) ? sme[oe3] : NEG;
    }

    for (int d = 1; d <= dfin; ++d) {
        float cb0 = nb0, cb1 = nb1, cb2 = nb2, cb3 = nb3;
        float ce0 = ne0, ce1 = ne1, ce2 = ne2, ce3 = ne3;

        // prefetch diagonal d+1 (independent of alpha chain)
        ob0 += SB; ob1 += SB; ob2 += SB; ob3 += SB;
        oe0 += SB; oe1 += SB; oe2 += SB; oe3 += SB;
        {
            int dn = d + 1;
            nb0 = (dn >= u0 + 1 && dn <= u0 + T - 1) ? smb[ob0] : NEG;
            nb1 = (dn >= u1 + 1 && dn <= u1 + T - 1) ? smb[ob1] : NEG;
            nb2 = (dn >= u2 + 1 && dn <= u2 + T - 1) ? smb[ob2] : NEG;
            nb3 = (dn >= u3 + 1 && dn <= u3 + T - 1) ? smb[ob3] : NEG;
            ne0 = (u0 >= 1 && u0 <= U && dn >= u0 && dn <= u0 + T - 1) ? sme[oe0] : NEG;
            ne1 = (u1 >= 1 && u1 <= U && dn >= u1 && dn <= u1 + T - 1) ? sme[oe1] : NEG;
            ne2 = (u2 <= U && dn >= u2 && dn <= u2 + T - 1) ? sme[oe2] : NEG;
            ne3 = (u3 <= U && dn >= u3 && dn <= u3 + T - 1) ? sme[oe3] : NEG;
        }

        // P[u-1] via rotate shfl; lane 0 wraps to lane 31's previous register
        float s0 = __shfl_sync(0xffffffffu, p0, src);
        float s1 = __shfl_sync(0xffffffffu, p1, src);
        float s2 = __shfl_sync(0xffffffffu, p2, src);
        float s3 = __shfl_sync(0xffffffffu, p3, src);
        float q0 = (lane == 0) ? NEG : s0;   // u=0 has no predecessor
        float q1 = (lane == 0) ? s0 : s1;
        float q2 = (lane == 0) ? s1 : s2;
        float q3 = (lane == 0) ? s2 : s3;

        p0 = laddexp2(p0 + cb0, q0 + ce0);
        p1 = laddexp2(p1 + cb1, q1 + ce1);
        p2 = laddexp2(p2 + cb2, q2 + ce2);
        p3 = laddexp2(p3 + cb3, q3 + ce3);

        if (d == dfin) {
            if (u0 == lab_len) afin = p0;
            if (u1 == lab_len) afin = p1;
            if (u2 == lab_len) afin = p2;
            if (u3 == lab_len) afin = p3;
        }
    }

    // Per-batch loss + fused mean via last-CTA reduction
    if (lane == (lab_len & 31)) {
        g_loss[b] = -LN2 * (afin + smb[tfin * SB + lab_len]);
        __threadfence();
        int done = atomicAdd(&g_ctr, 1);
        if (done == B - 1) {
            __threadfence();
            float sacc = 0.0f;
#pragma unroll
            for (int i = 0; i < B; ++i) sacc += *((volatile float*)&g_loss[i]);
            out[0] = sacc / (float)B;
            g_ctr = 0;                    // reset for next graph replay
        }
    }
}

extern "C" void kernel_launch(void* const* d_in, const int* in_sizes, int n_in,
                              void* d_out, int out_size) {
    const float* logits  = (const float*)d_in[0];
    const int*   targets = (const int*)d_in[1];
    const int*   fb      = (const int*)d_in[2];
    const int*   tl      = (const int*)d_in[3];

    cudaFuncSetAttribute(k_dp, cudaFuncAttributeMaxDynamicSharedMemorySize, SMEM_DP);

    int blocks = (NCELL * 32 + 255) / 256;  // one warp per cell
    k_lse<<<blocks, 256>>>(logits, targets, fb, tl);
    k_dp<<<B, 256, SMEM_DP>>>(fb, tl, (float*)d_out);
}

// round 17
// speedup vs baseline: 1.1512x; 1.1512x over previous
#include <cuda_runtime.h>

#define NEG (-1e30f)
#define LOG2E 1.4426950408889634f
#define LN2   0.6931471805599453f

constexpr int B  = 8;
constexpr int T  = 200;
constexpr int U1 = 101;
constexpr int V  = 512;
constexpr int U  = U1 - 1;
constexpr int D  = T + U1 - 1;           // 300 anti-diagonals
constexpr int NCELL = B * T * U1;
constexpr int SB = 102;                  // padded row stride (conflict-free anti-diagonal reads)
constexpr int K  = 5;                    // diagonals per barrier
constexpr int NTRI = K * (K + 1) / 2;    // 15 triangle cells

// Padded log2-prob tables: [b][t*SB + u]  (pre-scaled by log2 e)
__device__ float g_blank[B * T * SB];
__device__ float g_emit [B * T * SB];
__device__ float g_loss [B];
__device__ int   g_ctr;

__device__ __forceinline__ float ex2_(float x) {
    float r; asm("ex2.approx.ftz.f32 %0, %1;" : "=f"(r) : "f"(x)); return r;
}
__device__ __forceinline__ float lg2_(float x) {
    float r; asm("lg2.approx.ftz.f32 %0, %1;" : "=f"(r) : "f"(x)); return r;
}
__device__ __forceinline__ float laddexp2(float a, float b) {
    float mx = fmaxf(a, b);
    float dd = -fabsf(a - b);
    return mx + lg2_(1.0f + ex2_(dd));
}

// One warp per (b,t,u) cell: logsumexp over V=512; dead cells skipped;
// logits read-once via __ldcs (evict-first). (R13 champion version, verbatim.)
__global__ void __launch_bounds__(256) k_lse(const float* __restrict__ logits,
                                             const int*   __restrict__ targets,
                                             const int*   __restrict__ fbank_len,
                                             const int*   __restrict__ text_len) {
    int gw   = (blockIdx.x * blockDim.x + threadIdx.x) >> 5;
    int lane = threadIdx.x & 31;
    if (gw >= NCELL) return;

    int u = gw % U1;
    int t = (gw / U1) % T;
    int b = gw / (U1 * T);

    int lab_len = text_len[b] - 1;
    if (t >= fbank_len[b] || u > lab_len) return;   // never consumed by the DP

    const float4* p = reinterpret_cast<const float4*>(logits) + (size_t)gw * (V / 4);
    float4 v0 = __ldcs(p + lane);
    float4 v1 = __ldcs(p + lane + 32);
    float4 v2 = __ldcs(p + lane + 64);
    float4 v3 = __ldcs(p + lane + 96);

    float m = fmaxf(fmaxf(fmaxf(v0.x, v0.y), fmaxf(v0.z, v0.w)),
                    fmaxf(fmaxf(fmaxf(v1.x, v1.y), fmaxf(v1.z, v1.w)),
                          fmaxf(fmaxf(fmaxf(v2.x, v2.y), fmaxf(v2.z, v2.w)),
                                fmaxf(fmaxf(v3.x, v3.y), fmaxf(v3.z, v3.w)))));
#pragma unroll
    for (int o = 16; o; o >>= 1) m = fmaxf(m, __shfl_xor_sync(0xffffffffu, m, o));

    float s = __expf(v0.x - m) + __expf(v0.y - m) + __expf(v0.z - m) + __expf(v0.w - m)
            + __expf(v1.x - m) + __expf(v1.y - m) + __expf(v1.z - m) + __expf(v1.w - m)
            + __expf(v2.x - m) + __expf(v2.y - m) + __expf(v2.z - m) + __expf(v2.w - m)
            + __expf(v3.x - m) + __expf(v3.y - m) + __expf(v3.z - m) + __expf(v3.w - m);
#pragma unroll
    for (int o = 16; o; o >>= 1) s += __shfl_xor_sync(0xffffffffu, s, o);

    float lse = m + __logf(s);

    size_t base = (size_t)b * T * SB + t * SB + u;
    if (lane == 0) g_blank[base] = (v0.x - lse) * LOG2E;

    int lab = (u < U) ? targets[b * U1 + u + 1] : -1;
    if (lab >= 0) {
        int chunk = lab >> 2;
        if ((chunk & 31) == lane) {
            int j = chunk >> 5, c = lab & 3;
            float4 vv = (j == 0) ? v0 : (j == 1) ? v1 : (j == 2) ? v2 : v3;
            float ev  = (c == 0) ? vv.x : (c == 1) ? vv.y : (c == 2) ? vv.z : vv.w;
            g_emit[base] = (ev - lse) * LOG2E;
        }
    }
}

// ---- triangle chain (shared by both paths) ----
__device__ __forceinline__ void tri_chain(float (&bb)[K + 1],
                                          const float (&tb)[NTRI], const float (&te)[NTRI],
                                          int d0, int dfin, bool fin, float& afin) {
    int idx = 0;
#pragma unroll
    for (int i = 1; i <= K; ++i) {
#pragma unroll
        for (int j = 0; j <= K - i; ++j, ++idx)
            bb[j] = laddexp2(bb[j] + tb[idx], bb[j + 1] + te[idx]);
        if (fin && (d0 + i) == dfin) afin = bb[0];
    }
}

// K-diagonal-blocked alpha DP (R8 structure) + warp-uniform fast path:
// when ALL lanes of a warp have a fully in-bounds triangle, use unguarded
// affine-offset loads (zero predicates); else the R8 guarded loads.
constexpr int SMEM_DP = 2 * T * SB * (int)sizeof(float);

__global__ void __launch_bounds__(128, 1) k_dp(const int* __restrict__ fbank_len,
                                               const int* __restrict__ text_len,
                                               float* __restrict__ out) {
    extern __shared__ float sm[];
    float* smb = sm;                     // blank [T][SB]
    float* sme = sm + T * SB;            // emit  [T][SB]
    __shared__ float A[2][128 + K + 1];  // alpha on base diagonal, double-buffered

    int b   = blockIdx.x;
    int tid = threadIdx.x;
    int u   = tid;
    int w   = tid >> 5;

    {   // Stage tables (L2-resident, float4, layout matches padded gmem)
        const float4* gb4 = reinterpret_cast<const float4*>(g_blank + (size_t)b * T * SB);
        const float4* ge4 = reinterpret_cast<const float4*>(g_emit  + (size_t)b * T * SB);
        float4* sb4 = reinterpret_cast<float4*>(smb);
        float4* se4 = reinterpret_cast<float4*>(sme);
        for (int i = tid; i < T * SB / 4; i += 128) { sb4[i] = gb4[i]; se4[i] = ge4[i]; }
    }

    if (tid < K) { A[0][tid] = NEG; A[1][tid] = NEG; }
    A[0][u + K] = (u == 0) ? 0.0f : NEG;

    int lab_len = text_len[b] - 1;
    int tfin    = fbank_len[b] - 1;
    int dfin    = tfin + lab_len;
    bool fin    = (u == lab_len);
    float afin  = NEG;
    __syncthreads();

    // warp-uniform fast-path window: warps 1,2 only (u in [32,95]);
    // d0 >= u_max ensures t >= 1 for all (i,j); d0 <= T-1-K+u_min ensures t <= T-1.
    int u_min = w << 5;
    int u_max = u_min + 31;
    bool welig = (w == 1) || (w == 2);
    int d_lo = u_max;
    int d_hi = T - 1 - K + u_min;

    int buf = 0;
    for (int d0 = 0; d0 < dfin; d0 += K) {
        float bb[K + 1];
#pragma unroll
        for (int j = 0; j <= K; ++j) bb[j] = A[buf][u - j + K];

        float tb[NTRI], te[NTRI];
        if (welig && d0 >= d_lo && d0 <= d_hi) {
            // ---- fast path: fully in-bounds, unguarded affine loads ----
            int base_s = (d0 - 1 - u) * SB + u;          // blank(t-1, u-j)
            int base_m = (d0 - u) * SB + u - 1;          // emit (t,   u-j-1)
            int idx = 0;
#pragma unroll
            for (int i = 1; i <= K; ++i) {
#pragma unroll
                for (int j = 0; j <= K - i; ++j, ++idx) {
                    tb[idx] = smb[base_s + i * SB + j * (SB - 1)];
                    te[idx] = sme[base_m + i * SB + j * (SB - 1)];
                }
            }
        } else {
            // ---- slow path: R8 guarded loads (bit-identical behavior) ----
            int idx = 0;
#pragma unroll
            for (int i = 1; i <= K; ++i) {
#pragma unroll
                for (int j = 0; j <= K - i; ++j, ++idx) {
                    int up = u - j;
                    int t  = d0 + i - up;
                    bool vs = (t >= 1 && t < T && up >= 0 && up < U1);
                    bool vm = (t >= 0 && t < T && up >= 1 && up < U1);
                    tb[idx] = vs ? smb[(t - 1) * SB + up] : NEG;
                    te[idx] = vm ? sme[t * SB + (up - 1)] : NEG;
                }
            }
        }

        tri_chain(bb, tb, te, d0, dfin, fin, afin);

        A[buf ^ 1][u + K] = bb[0];
        __syncthreads();
        buf ^= 1;
    }

    // Per-batch loss + fused mean via last-CTA reduction
    if (fin) {
        g_loss[b] = -LN2 * (afin + smb[tfin * SB + lab_len]);
        __threadfence();
        int done = atomicAdd(&g_ctr, 1);
        if (done == B - 1) {
            __threadfence();
            float s = 0.0f;
#pragma unroll
            for (int i = 0; i < B; ++i) s += *((volatile float*)&g_loss[i]);
            out[0] = s / (float)B;
            g_ctr = 0;                    // reset for next graph replay
        }
    }
}

extern "C" void kernel_launch(void* const* d_in, const int* in_sizes, int n_in,
                              void* d_out, int out_size) {
    const float* logits  = (const float*)d_in[0];
    const int*   targets = (const int*)d_in[1];
    const int*   fb      = (const int*)d_in[2];
    const int*   tl      = (const int*)d_in[3];

    cudaFuncSetAttribute(k_dp, cudaFuncAttributeMaxDynamicSharedMemorySize, SMEM_DP);

    int blocks = (NCELL * 32 + 255) / 256;  // one warp per cell
    k_lse<<<blocks, 256>>>(logits, targets, fb, tl);
    k_dp<<<B, 128, SMEM_DP>>>(fb, tl, (float*)d_out);
}